// round 13
// baseline (speedup 1.0000x reference)
#include <cuda_runtime.h>
#include <cuda_bf16.h>
#include <cuda_fp16.h>
#include <cstdint>

#define NMAX 50000
#define HID 128

// ---------------- scratch ----------------
__device__ __align__(16) float g_bufA[NMAX * HID];
__device__ __align__(16) float g_bufB[NMAX * HID];
__device__ float g_mask[NMAX];
__device__ float g_colsum[HID];
__device__ float g_colsq[HID];
__device__ float g_bnscale[2][HID];
__device__ float g_bnshift[2][HID];
// transposed weights ([n][k] fp16, single rounded copy): W1T(128x256) then 5x(128x128)
__device__ __align__(16) __half g_Bt16[32768 + 5 * 16384];

// ---------------- helpers ----------------
__device__ __forceinline__ uint32_t smem_u32(const void* p) {
    uint32_t a;
    asm("{ .reg .u64 t; cvta.to.shared.u64 t, %1; cvt.u32.u64 %0, t; }"
        : "=r"(a) : "l"(p));
    return a;
}
__device__ __forceinline__ void ldsm4(uint32_t* r, uint32_t addr) {
    asm volatile("ldmatrix.sync.aligned.m8n8.x4.shared.b16 {%0,%1,%2,%3}, [%4];"
                 : "=r"(r[0]), "=r"(r[1]), "=r"(r[2]), "=r"(r[3]) : "r"(addr));
}
__device__ __forceinline__ void mma16816(float* c, const uint32_t* a, const uint32_t* b) {
    asm volatile(
        "mma.sync.aligned.m16n8k16.row.col.f32.f16.f16.f32 "
        "{%0,%1,%2,%3}, {%4,%5,%6,%7}, {%8,%9}, {%0,%1,%2,%3};"
        : "+f"(c[0]), "+f"(c[1]), "+f"(c[2]), "+f"(c[3])
        : "r"(a[0]), "r"(a[1]), "r"(a[2]), "r"(a[3]), "r"(b[0]), "r"(b[1]));
}
__device__ __forceinline__ void cpasync16(uint32_t dst, const void* src) {
    asm volatile("cp.async.cg.shared.global [%0], [%1], 16;" :: "r"(dst), "l"(src));
}
#define CP_COMMIT() asm volatile("cp.async.commit_group;" ::: "memory")
#define CP_WAIT0() asm volatile("cp.async.wait_group 0;" ::: "memory")

__device__ __forceinline__ uint32_t pack_h2(__half a, __half b) {
    return ((uint32_t)__half_as_ushort(b) << 16) | (uint32_t)__half_as_ushort(a);
}
// XOR-swizzled offset inside a tile with 256B row stride (128 fp16 cols)
__device__ __forceinline__ uint32_t swzb(int r, int kbyte) {
    return (uint32_t)r * 256u + (uint32_t)(kbyte ^ ((r & 7) << 4));
}

// ---------------- small kernels ----------------
__global__ void k_init(float* mask, int n) {
    int i = blockIdx.x * blockDim.x + threadIdx.x;
    if (i < n) mask[i] = 0.f;
    if (i < HID) { g_colsum[i] = 0.f; g_colsq[i] = 0.f; }
}
__global__ void k_scatter(const int* __restrict__ dst, int E, float* __restrict__ mask) {
    int e = blockIdx.x * blockDim.x + threadIdx.x;
    if (e < E) mask[dst[e]] = 1.0f;
}
__global__ void k_finalize(const float* __restrict__ g, const float* __restrict__ beta,
                           int idx, int n) {
    int c = threadIdx.x;
    float inv = 1.0f / (float)n;
    float mean = g_colsum[c] * inv;
    float var = g_colsq[c] * inv - mean * mean;
    float sc = g[c] * rsqrtf(var + 1e-5f);
    g_bnscale[idx][c] = sc;
    g_bnshift[idx][c] = beta[c] - sc * mean;
    g_colsum[c] = 0.f;
    g_colsq[c] = 0.f;
}
// transpose weights into [n][k] fp16 (single rounded copy)
__global__ void k_prep(const float* __restrict__ W1, const float* __restrict__ W2,
                       const float* __restrict__ Wv, const float* __restrict__ Wo) {
    int m = blockIdx.y;
    const float* src; int K, off;
    switch (m) {
        case 0: src = W1; K = 256; off = 0; break;
        case 1: src = W2; K = 128; off = 32768; break;
        case 2: src = Wv; K = 128; off = 49152; break;
        case 3: src = Wo; K = 128; off = 65536; break;
        case 4: src = Wv + 16384; K = 128; off = 81920; break;
        default: src = Wo + 16384; K = 128; off = 98304; break;
    }
    int idx = blockIdx.x * 256 + threadIdx.x;
    if (idx < K * 128) {
        int k = idx >> 7, nn = idx & 127;
        g_Bt16[off + nn * K + k] = __float2half_rn(src[idx]);
    }
}

// ---------------- staging (256 threads, 64-row act tiles) ----------------
// exact fp16 hi/lo split of fp32 activations
__device__ __forceinline__ void split_store(float4 v, int r, int kk, char* dH, char* dL) {
    __half h0 = __float2half_rn(v.x), h1 = __float2half_rn(v.y);
    __half h2 = __float2half_rn(v.z), h3 = __float2half_rn(v.w);
    __half l0 = __float2half_rn(v.x - __half2float(h0));
    __half l1 = __float2half_rn(v.y - __half2float(h1));
    __half l2 = __float2half_rn(v.z - __half2float(h2));
    __half l3 = __float2half_rn(v.w - __half2float(h3));
    uint32_t so = swzb(r, kk * 2);
    *(uint2*)(dH + so) = make_uint2(pack_h2(h0, h1), pack_h2(h2, h3));
    *(uint2*)(dL + so) = make_uint2(pack_h2(l0, l1), pack_h2(l2, l3));
}
template <int PRO>
__device__ __forceinline__ float4 bn_tf(float4 v, int gk, int bnIdx) {
    if (PRO) {
        const float* sc = g_bnscale[bnIdx];
        const float* sh = g_bnshift[bnIdx];
        v.x = fmaxf(fmaf(sc[gk + 0], v.x, sh[gk + 0]), 0.f);
        v.y = fmaxf(fmaf(sc[gk + 1], v.y, sh[gk + 1]), 0.f);
        v.z = fmaxf(fmaf(sc[gk + 2], v.z, sh[gk + 2]), 0.f);
        v.w = fmaxf(fmaf(sc[gk + 3], v.w, sh[gk + 3]), 0.f);
    }
    return v;
}
// 64 rows x 128 cols fp32 -> fp16 hi/lo swizzled (256 threads)
template <int PRO>
__device__ __forceinline__ void stage_act(const float* __restrict__ A, int Kld, int kcol0,
                                          int rowBase, int n, char* dH, char* dL,
                                          int bnIdx, int tid) {
#pragma unroll
    for (int it = 0; it < 8; it++) {
        int f4 = tid + 256 * it;
        int r = f4 >> 5;
        int kk = (f4 & 31) * 4;
        int row = rowBase + r;
        float4 v = make_float4(0.f, 0.f, 0.f, 0.f);
        if (row < n) v = *(const float4*)(A + (size_t)row * Kld + kcol0 + kk);
        v = bn_tf<PRO>(v, kcol0 + kk, bnIdx);
        split_store(v, r, kk, dH, dL);
    }
}
// async weight stage: full 128n x 128k fp16 chunk (32KB) via cp.async
__device__ __forceinline__ void stage_w_async(const __half* __restrict__ W, int Kw,
                                              int k0, uint32_t dW, int tid) {
#pragma unroll
    for (int it = 0; it < 8; it++) {
        int idx = tid + 256 * it;
        int nr = idx >> 4;
        int kg = (idx & 15) * 16;
        uint32_t so = swzb(nr, kg);
        cpasync16(dW + so, (const char*)W + (size_t)nr * Kw * 2 + k0 * 2 + kg);
    }
}

// ---------------- warp GEMM: 32x32 per warp, 2x4 warp grid, 2-pass A-hi/lo ----------
__device__ __forceinline__ void gemm_tile(uint32_t sAH, uint32_t sAL, uint32_t sW,
                                          float acc[2][4][4], int wm, int wn, int lane) {
    const uint32_t aBase = (uint32_t)(wm * 32 + (lane & 15)) * 256u;
    const uint32_t aXor = (uint32_t)(((wm * 32 + (lane & 15)) & 7) << 4);
    const int aKb = (lane >> 4) * 16;
    const int nB = wn * 32 + (lane & 7) + ((lane & 16) ? 8 : 0);
    const uint32_t bBase = (uint32_t)nB * 256u;
    const uint32_t bXor = (uint32_t)((nB & 7) << 4);
    const int bKb = (lane & 8) ? 16 : 0;

#pragma unroll
    for (int ks = 0; ks < 8; ks++) {
        const int kb = ks * 32;
        uint32_t Ah[2][4], Al[2][4], Bh[2][4];
#pragma unroll
        for (int t = 0; t < 2; t++) {
            uint32_t off = aBase + (uint32_t)t * 4096u + (uint32_t)((kb + aKb) ^ (int)aXor);
            ldsm4(Ah[t], sAH + off);
            ldsm4(Al[t], sAL + off);
        }
#pragma unroll
        for (int g = 0; g < 2; g++) {
            uint32_t off = bBase + (uint32_t)g * 4096u + (uint32_t)((kb + bKb) ^ (int)bXor);
            ldsm4(Bh[g], sW + off);
        }
        // pass-major: consecutive MMAs hit different accumulators
#pragma unroll
        for (int t = 0; t < 2; t++)
#pragma unroll
            for (int nt = 0; nt < 4; nt++)
                mma16816(acc[t][nt], Ah[t], &Bh[nt >> 1][(nt & 1) * 2]);
#pragma unroll
        for (int t = 0; t < 2; t++)
#pragma unroll
            for (int nt = 0; nt < 4; nt++)
                mma16816(acc[t][nt], Al[t], &Bh[nt >> 1][(nt & 1) * 2]);
    }
}

// ---------------- encoder GEMM kernel (fp32 out + fused BN stats) ----------------
// smem: aH(16K) aL(16K) w(32K) stats(1K) = 65KB; regs<=84 -> 3 CTAs/SM
#define OFF_AL 16384
#define OFF_W 32768
#define OFF_ST 65536
#define ENC_SMEM (65536 + 1024)
template <int KC, int PRO>
__global__ void __launch_bounds__(256, 3)
k_enc(const float* __restrict__ A, int btOff, const float* __restrict__ bias,
      float* __restrict__ out, int n, int bnIdx) {
    extern __shared__ char smem[];
    char* aH = smem;
    char* aL = smem + OFF_AL;
    float* ssum = (float*)(smem + OFF_ST);
    float* ssq = ssum + 128;
    const uint32_t sb = smem_u32(smem);
    const int tid = threadIdx.x, lane = tid & 31, wid = tid >> 5;
    const int wm = wid & 1, wn = wid >> 1;
    const int rowBase = blockIdx.x * 64;
    const int Kw = KC * 128;
    const __half* W = g_Bt16 + btOff;

    if (tid < 128) { ssum[tid] = 0.f; ssq[tid] = 0.f; }

    float acc[2][4][4];
#pragma unroll
    for (int t = 0; t < 2; t++)
#pragma unroll
        for (int nt = 0; nt < 4; nt++)
#pragma unroll
            for (int j = 0; j < 4; j++) acc[t][nt][j] = 0.f;

    // prefetch W chunk0 (async) + stage A chunk0 (direct)
    stage_w_async(W, Kw, 0, sb + OFF_W, tid);
    CP_COMMIT();
    stage_act<PRO>(A, Kw, 0, rowBase, n, aH, aL, bnIdx, tid);
    CP_WAIT0();
    __syncthreads();

    gemm_tile(sb, sb + OFF_AL, sb + OFF_W, acc, wm, wn, lane);

    if (KC == 2) {
        __syncthreads();  // all reads done -> reuse W/A buffers in place
        stage_w_async(W, Kw, 128, sb + OFF_W, tid);
        CP_COMMIT();
        stage_act<PRO>(A, Kw, 128, rowBase, n, aH, aL, bnIdx, tid);
        CP_WAIT0();
        __syncthreads();
        gemm_tile(sb, sb + OFF_AL, sb + OFF_W, acc, wm, wn, lane);
    }

    // epilogue: bias, store fp32, fused column stats
    const int r0 = rowBase + wm * 32 + (lane >> 2);
    const int colb = wn * 32 + (lane & 3) * 2;
#pragma unroll
    for (int nt = 0; nt < 4; nt++) {
        int cc = colb + nt * 8;
        float bx = bias[cc], by = bias[cc + 1];
        float p0 = 0.f, p1 = 0.f, q0 = 0.f, q1 = 0.f;
#pragma unroll
        for (int t = 0; t < 2; t++) {
#pragma unroll
            for (int h = 0; h < 2; h++) {
                int row = r0 + t * 16 + h * 8;
                float y0 = acc[t][nt][h * 2] + bx;
                float y1 = acc[t][nt][h * 2 + 1] + by;
                if (row < n) {
                    *(float2*)(out + (size_t)row * HID + cc) = make_float2(y0, y1);
                    p0 += y0; q0 += y0 * y0;
                    p1 += y1; q1 += y1 * y1;
                }
            }
        }
#pragma unroll
        for (int m = 4; m <= 16; m <<= 1) {
            p0 += __shfl_xor_sync(~0u, p0, m);
            p1 += __shfl_xor_sync(~0u, p1, m);
            q0 += __shfl_xor_sync(~0u, q0, m);
            q1 += __shfl_xor_sync(~0u, q1, m);
        }
        if ((lane >> 2) == 0) {
            atomicAdd(&ssum[cc], p0);
            atomicAdd(&ssum[cc + 1], p1);
            atomicAdd(&ssq[cc], q0);
            atomicAdd(&ssq[cc + 1], q1);
        }
    }
    __syncthreads();
    if (tid < 128) {
        atomicAdd(&g_colsum[tid], ssum[tid]);
        atomicAdd(&g_colsq[tid], ssq[tid]);
    }
}

// ---------------- fused 4-GEMM attention kernel ----------------
// smem: aH(16K) aL(16K) w(32K) = 64KB; regs<=84 -> 3 CTAs/SM
#define FUS_SMEM 65536
__global__ void __launch_bounds__(256, 3)
k_fused(const float* __restrict__ A, const float* __restrict__ bv,
        const float* __restrict__ bo, float* __restrict__ out, int n) {
    extern __shared__ char smem[];
    const uint32_t sb = smem_u32(smem);
    const int tid = threadIdx.x, lane = tid & 31, wid = tid >> 5;
    const int wm = wid & 1, wn = wid >> 1;
    const int rowBase = blockIdx.x * 64;

    const int woffs[4] = {49152, 65536, 81920, 98304};
    const float* biases[4] = {bv, bo, bv + HID, bo + HID};

    // prefetch W0 + initial act stage (BN#1 + relu on y2)
    stage_w_async(g_Bt16 + woffs[0], 128, 0, sb + OFF_W, tid);
    CP_COMMIT();
    stage_act<1>(A, 128, 0, rowBase, n, smem, smem + OFF_AL, 1, tid);
    CP_WAIT0();
    __syncthreads();

    float mk[2][2];
#pragma unroll
    for (int t = 0; t < 2; t++)
#pragma unroll
        for (int h = 0; h < 2; h++) {
            int row = rowBase + wm * 32 + t * 16 + h * 8 + (lane >> 2);
            mk[t][h] = (row < n) ? g_mask[row] : 0.f;
        }

    for (int s = 0; s < 4; s++) {
        float acc[2][4][4];
#pragma unroll
        for (int t = 0; t < 2; t++)
#pragma unroll
            for (int nt = 0; nt < 4; nt++)
#pragma unroll
                for (int j = 0; j < 4; j++) acc[t][nt][j] = 0.f;

        gemm_tile(sb, sb + OFF_AL, sb + OFF_W, acc, wm, wn, lane);
        __syncthreads();  // all reads of act+W done -> safe to overwrite both

        if (s < 3) {
            stage_w_async(g_Bt16 + woffs[s + 1], 128, 0, sb + OFF_W, tid);
            CP_COMMIT();
        }

        const float* bias = biases[s];
        const bool isMask = (s & 1) == 0;
        const bool last = (s == 3);
        const int colb = wn * 32 + (lane & 3) * 2;
#pragma unroll
        for (int nt = 0; nt < 4; nt++) {
            int cc = colb + nt * 8;
            float bx = bias[cc], by = bias[cc + 1];
#pragma unroll
            for (int t = 0; t < 2; t++) {
#pragma unroll
                for (int h = 0; h < 2; h++) {
                    float y0 = acc[t][nt][h * 2] + bx;
                    float y1 = acc[t][nt][h * 2 + 1] + by;
                    if (isMask) {
                        y0 *= mk[t][h];
                        y1 *= mk[t][h];
                    } else {
                        y0 = fmaxf(y0, 0.f);
                        y1 = fmaxf(y1, 0.f);
                    }
                    int rl = wm * 32 + t * 16 + h * 8 + (lane >> 2);
                    if (last) {
                        int row = rowBase + rl;
                        if (row < n)
                            *(float2*)(out + (size_t)row * HID + cc) = make_float2(y0, y1);
                    } else {
                        __half h0 = __float2half_rn(y0);
                        __half h1 = __float2half_rn(y1);
                        uint32_t hi = pack_h2(h0, h1);
                        uint32_t lo = pack_h2(__float2half_rn(y0 - __half2float(h0)),
                                              __float2half_rn(y1 - __half2float(h1)));
                        uint32_t so = swzb(rl, cc * 2);
                        *(uint32_t*)(smem + so) = hi;
                        *(uint32_t*)(smem + OFF_AL + so) = lo;
                    }
                }
            }
        }
        if (!last) {
            CP_WAIT0();
            __syncthreads();  // epilogue visible + next weights ready
        }
    }
}

// ---------------- launch ----------------
extern "C" void kernel_launch(void* const* d_in, const int* in_sizes, int n_in,
                              void* d_out, int out_size) {
    const float* x   = (const float*)d_in[0];
    const int*   ei  = (const int*)d_in[1];
    const float* W1  = (const float*)d_in[2];
    const float* b1  = (const float*)d_in[3];
    const float* g1  = (const float*)d_in[4];
    const float* be1 = (const float*)d_in[5];
    const float* W2  = (const float*)d_in[6];
    const float* b2  = (const float*)d_in[7];
    const float* g2  = (const float*)d_in[8];
    const float* be2 = (const float*)d_in[9];
    // d_in[10..13] = Wq,bq,Wk,bk : mathematically unused (softmax over dst sums to 1)
    const float* Wv  = (const float*)d_in[14];
    const float* bv  = (const float*)d_in[15];
    const float* Wo  = (const float*)d_in[16];
    const float* bo  = (const float*)d_in[17];
    float* out = (float*)d_out;

    const int n = in_sizes[0] / 256;
    const int E = in_sizes[1] / 2;
    const int* dst = ei + E;

    float *bufA, *bufB, *mask;
    cudaGetSymbolAddress((void**)&bufA, g_bufA);
    cudaGetSymbolAddress((void**)&bufB, g_bufB);
    cudaGetSymbolAddress((void**)&mask, g_mask);

    cudaFuncSetAttribute(k_enc<2, 0>, cudaFuncAttributeMaxDynamicSharedMemorySize, ENC_SMEM);
    cudaFuncSetAttribute(k_enc<1, 1>, cudaFuncAttributeMaxDynamicSharedMemorySize, ENC_SMEM);
    cudaFuncSetAttribute(k_fused, cudaFuncAttributeMaxDynamicSharedMemorySize, FUS_SMEM);

    const int gblk = (n + 63) / 64;

    k_prep<<<dim3(128, 6), 256>>>(W1, W2, Wv, Wo);
    k_init<<<(n + 255) / 256, 256>>>(mask, n);
    k_scatter<<<(E + 255) / 256, 256>>>(dst, E, mask);

    // encoder layer 1: y1 = x @ W1 + b1 (stats fused) -> BN #0
    k_enc<2, 0><<<gblk, 256, ENC_SMEM>>>(x, 0, b1, bufA, n, 0);
    k_finalize<<<1, 128>>>(g1, be1, 0, n);

    // encoder layer 2: y2 = relu(bn0(y1)) @ W2 + b2 (stats fused) -> BN #1
    k_enc<1, 1><<<gblk, 256, ENC_SMEM>>>(bufA, 32768, b2, bufB, n, 0);
    k_finalize<<<1, 128>>>(g2, be2, 1, n);

    // fused attention stack (Wv0/mask -> Wo0/relu -> Wv1/mask -> Wo1/relu)
    k_fused<<<gblk, 256, FUS_SMEM>>>(bufB, bv, bo, out, n);
}

// round 14
// speedup vs baseline: 1.0664x; 1.0664x over previous
#include <cuda_runtime.h>
#include <cuda_bf16.h>
#include <cuda_fp16.h>
#include <cstdint>

#define NMAX 50000
#define HID 128

// ---------------- scratch ----------------
__device__ __align__(16) float g_bufA[NMAX * HID];
__device__ __align__(16) float g_bufB[NMAX * HID];
__device__ float g_mask[NMAX];
__device__ float g_colsum[HID];
__device__ float g_colsq[HID];
__device__ float g_bnscale[2][HID];
__device__ float g_bnshift[2][HID];
// transposed weights ([n][k] fp16, single rounded copy): W1T(128x256) then 5x(128x128)
__device__ __align__(16) __half g_Bt16[32768 + 5 * 16384];

// ---------------- helpers ----------------
__device__ __forceinline__ uint32_t smem_u32(const void* p) {
    uint32_t a;
    asm("{ .reg .u64 t; cvta.to.shared.u64 t, %1; cvt.u32.u64 %0, t; }"
        : "=r"(a) : "l"(p));
    return a;
}
__device__ __forceinline__ void ldsm4(uint32_t* r, uint32_t addr) {
    asm volatile("ldmatrix.sync.aligned.m8n8.x4.shared.b16 {%0,%1,%2,%3}, [%4];"
                 : "=r"(r[0]), "=r"(r[1]), "=r"(r[2]), "=r"(r[3]) : "r"(addr));
}
__device__ __forceinline__ void mma16816(float* c, const uint32_t* a, const uint32_t* b) {
    asm volatile(
        "mma.sync.aligned.m16n8k16.row.col.f32.f16.f16.f32 "
        "{%0,%1,%2,%3}, {%4,%5,%6,%7}, {%8,%9}, {%0,%1,%2,%3};"
        : "+f"(c[0]), "+f"(c[1]), "+f"(c[2]), "+f"(c[3])
        : "r"(a[0]), "r"(a[1]), "r"(a[2]), "r"(a[3]), "r"(b[0]), "r"(b[1]));
}
__device__ __forceinline__ void cpasync16(uint32_t dst, const void* src) {
    asm volatile("cp.async.cg.shared.global [%0], [%1], 16;" :: "r"(dst), "l"(src));
}
#define CP_COMMIT() asm volatile("cp.async.commit_group;" ::: "memory")
#define CP_WAIT0() asm volatile("cp.async.wait_group 0;" ::: "memory")
#define CP_WAIT1() asm volatile("cp.async.wait_group 1;" ::: "memory")

__device__ __forceinline__ uint32_t pack_h2(__half a, __half b) {
    return ((uint32_t)__half_as_ushort(b) << 16) | (uint32_t)__half_as_ushort(a);
}
// XOR-swizzled offset inside a tile with 256B row stride (128 fp16 cols)
__device__ __forceinline__ uint32_t swzb(int r, int kbyte) {
    return (uint32_t)r * 256u + (uint32_t)(kbyte ^ ((r & 7) << 4));
}

// ---------------- small kernels ----------------
__global__ void k_init(float* mask, int n) {
    int i = blockIdx.x * blockDim.x + threadIdx.x;
    if (i < n) mask[i] = 0.f;
    if (i < HID) { g_colsum[i] = 0.f; g_colsq[i] = 0.f; }
}
__global__ void k_scatter(const int* __restrict__ dst, int E, float* __restrict__ mask) {
    int e = blockIdx.x * blockDim.x + threadIdx.x;
    if (e < E) mask[dst[e]] = 1.0f;
}
__global__ void k_finalize(const float* __restrict__ g, const float* __restrict__ beta,
                           int idx, int n) {
    int c = threadIdx.x;
    float inv = 1.0f / (float)n;
    float mean = g_colsum[c] * inv;
    float var = g_colsq[c] * inv - mean * mean;
    float sc = g[c] * rsqrtf(var + 1e-5f);
    g_bnscale[idx][c] = sc;
    g_bnshift[idx][c] = beta[c] - sc * mean;
    g_colsum[c] = 0.f;
    g_colsq[c] = 0.f;
}
// transpose weights into [n][k] fp16 (single rounded copy)
__global__ void k_prep(const float* __restrict__ W1, const float* __restrict__ W2,
                       const float* __restrict__ Wv, const float* __restrict__ Wo) {
    int m = blockIdx.y;
    const float* src; int K, off;
    switch (m) {
        case 0: src = W1; K = 256; off = 0; break;
        case 1: src = W2; K = 128; off = 32768; break;
        case 2: src = Wv; K = 128; off = 49152; break;
        case 3: src = Wo; K = 128; off = 65536; break;
        case 4: src = Wv + 16384; K = 128; off = 81920; break;
        default: src = Wo + 16384; K = 128; off = 98304; break;
    }
    int idx = blockIdx.x * 256 + threadIdx.x;
    if (idx < K * 128) {
        int k = idx >> 7, nn = idx & 127;
        g_Bt16[off + nn * K + k] = __float2half_rn(src[idx]);
    }
}

// ---------------- staging (256 threads, 64-row act tiles) ----------------
// exact fp16 hi/lo split of fp32 activations
__device__ __forceinline__ void split_store(float4 v, int r, int kk, char* dH, char* dL) {
    __half h0 = __float2half_rn(v.x), h1 = __float2half_rn(v.y);
    __half h2 = __float2half_rn(v.z), h3 = __float2half_rn(v.w);
    __half l0 = __float2half_rn(v.x - __half2float(h0));
    __half l1 = __float2half_rn(v.y - __half2float(h1));
    __half l2 = __float2half_rn(v.z - __half2float(h2));
    __half l3 = __float2half_rn(v.w - __half2float(h3));
    uint32_t so = swzb(r, kk * 2);
    *(uint2*)(dH + so) = make_uint2(pack_h2(h0, h1), pack_h2(h2, h3));
    *(uint2*)(dL + so) = make_uint2(pack_h2(l0, l1), pack_h2(l2, l3));
}
template <int PRO>
__device__ __forceinline__ float4 bn_tf(float4 v, int gk, int bnIdx) {
    if (PRO) {
        const float* sc = g_bnscale[bnIdx];
        const float* sh = g_bnshift[bnIdx];
        v.x = fmaxf(fmaf(sc[gk + 0], v.x, sh[gk + 0]), 0.f);
        v.y = fmaxf(fmaf(sc[gk + 1], v.y, sh[gk + 1]), 0.f);
        v.z = fmaxf(fmaf(sc[gk + 2], v.z, sh[gk + 2]), 0.f);
        v.w = fmaxf(fmaf(sc[gk + 3], v.w, sh[gk + 3]), 0.f);
    }
    return v;
}
// 64 rows x 128 cols fp32 -> fp16 hi/lo swizzled (256 threads)
template <int PRO>
__device__ __forceinline__ void stage_act(const float* __restrict__ A, int Kld, int kcol0,
                                          int rowBase, int n, char* dH, char* dL,
                                          int bnIdx, int tid) {
#pragma unroll
    for (int it = 0; it < 8; it++) {
        int f4 = tid + 256 * it;
        int r = f4 >> 5;
        int kk = (f4 & 31) * 4;
        int row = rowBase + r;
        float4 v = make_float4(0.f, 0.f, 0.f, 0.f);
        if (row < n) v = *(const float4*)(A + (size_t)row * Kld + kcol0 + kk);
        v = bn_tf<PRO>(v, kcol0 + kk, bnIdx);
        split_store(v, r, kk, dH, dL);
    }
}
// async weight stage: full 128n x 128k fp16 chunk (32KB) via cp.async
__device__ __forceinline__ void stage_w_async(const __half* __restrict__ W, int Kw,
                                              int k0, uint32_t dW, int tid) {
#pragma unroll
    for (int it = 0; it < 8; it++) {
        int idx = tid + 256 * it;
        int nr = idx >> 4;
        int kg = (idx & 15) * 16;
        uint32_t so = swzb(nr, kg);
        cpasync16(dW + so, (const char*)W + (size_t)nr * Kw * 2 + k0 * 2 + kg);
    }
}

// ---------------- warp GEMM: 32x32 per warp, 2x4 warp grid, 2-pass A-hi/lo ----------
// simple variant (for 3-CTA fused kernel, 84-reg cap)
__device__ __forceinline__ void gemm_tile_simple(uint32_t sAH, uint32_t sAL, uint32_t sW,
                                                 float acc[2][4][4], int wm, int wn,
                                                 int lane) {
    const uint32_t aBase = (uint32_t)(wm * 32 + (lane & 15)) * 256u;
    const uint32_t aXor = (uint32_t)(((wm * 32 + (lane & 15)) & 7) << 4);
    const int aKb = (lane >> 4) * 16;
    const int nB = wn * 32 + (lane & 7) + ((lane & 16) ? 8 : 0);
    const uint32_t bBase = (uint32_t)nB * 256u;
    const uint32_t bXor = (uint32_t)((nB & 7) << 4);
    const int bKb = (lane & 8) ? 16 : 0;

#pragma unroll
    for (int ks = 0; ks < 8; ks++) {
        const int kb = ks * 32;
        uint32_t Ah[2][4], Al[2][4], Bh[2][4];
#pragma unroll
        for (int t = 0; t < 2; t++) {
            uint32_t off = aBase + (uint32_t)t * 4096u + (uint32_t)((kb + aKb) ^ (int)aXor);
            ldsm4(Ah[t], sAH + off);
            ldsm4(Al[t], sAL + off);
        }
#pragma unroll
        for (int g = 0; g < 2; g++) {
            uint32_t off = bBase + (uint32_t)g * 4096u + (uint32_t)((kb + bKb) ^ (int)bXor);
            ldsm4(Bh[g], sW + off);
        }
#pragma unroll
        for (int t = 0; t < 2; t++)
#pragma unroll
            for (int nt = 0; nt < 4; nt++)
                mma16816(acc[t][nt], Ah[t], &Bh[nt >> 1][(nt & 1) * 2]);
#pragma unroll
        for (int t = 0; t < 2; t++)
#pragma unroll
            for (int nt = 0; nt < 4; nt++)
                mma16816(acc[t][nt], Al[t], &Bh[nt >> 1][(nt & 1) * 2]);
    }
}
// pipelined variant (for 2-CTA enc kernels): double-buffered LDSM fragments
__device__ __forceinline__ void gemm_tile_pipe(uint32_t sAH, uint32_t sAL, uint32_t sW,
                                               float acc[2][4][4], int wm, int wn,
                                               int lane) {
    const uint32_t aBase = (uint32_t)(wm * 32 + (lane & 15)) * 256u;
    const uint32_t aXor = (uint32_t)(((wm * 32 + (lane & 15)) & 7) << 4);
    const int aKb = (lane >> 4) * 16;
    const int nB = wn * 32 + (lane & 7) + ((lane & 16) ? 8 : 0);
    const uint32_t bBase = (uint32_t)nB * 256u;
    const uint32_t bXor = (uint32_t)((nB & 7) << 4);
    const int bKb = (lane & 8) ? 16 : 0;

    uint32_t Ah[2][2][4], Al[2][2][4], Bh[2][2][4];

    auto loadf = [&](int ks, int buf) {
        const int kb = ks * 32;
#pragma unroll
        for (int t = 0; t < 2; t++) {
            uint32_t off = aBase + (uint32_t)t * 4096u + (uint32_t)((kb + aKb) ^ (int)aXor);
            ldsm4(Ah[buf][t], sAH + off);
            ldsm4(Al[buf][t], sAL + off);
        }
#pragma unroll
        for (int g = 0; g < 2; g++) {
            uint32_t off = bBase + (uint32_t)g * 4096u + (uint32_t)((kb + bKb) ^ (int)bXor);
            ldsm4(Bh[buf][g], sW + off);
        }
    };

    loadf(0, 0);
#pragma unroll
    for (int ks = 0; ks < 8; ks++) {
        const int cur = ks & 1;
        if (ks < 7) loadf(ks + 1, cur ^ 1);  // prefetch next fragments under MMAs
#pragma unroll
        for (int t = 0; t < 2; t++)
#pragma unroll
            for (int nt = 0; nt < 4; nt++)
                mma16816(acc[t][nt], Ah[cur][t], &Bh[cur][nt >> 1][(nt & 1) * 2]);
#pragma unroll
        for (int t = 0; t < 2; t++)
#pragma unroll
            for (int nt = 0; nt < 4; nt++)
                mma16816(acc[t][nt], Al[cur][t], &Bh[cur][nt >> 1][(nt & 1) * 2]);
    }
}

// ---------------- encoder GEMM kernel (fp32 out + fused BN stats) ----------------
// smem: aH(16K) aL(16K) w(32K) araw(32K) stats(1K) = 97KB -> 2 CTAs/SM
#define OFF_AL 16384
#define OFF_W 32768
#define OFF_ARAW 65536
#define OFF_ST 98304
#define ENC_SMEM (98304 + 1024)
template <int KC, int PRO>
__global__ void __launch_bounds__(256, 2)
k_enc(const float* __restrict__ A, int btOff, const float* __restrict__ bias,
      float* __restrict__ out, int n, int bnIdx) {
    extern __shared__ char smem[];
    char* aH = smem;
    char* aL = smem + OFF_AL;
    float* ssum = (float*)(smem + OFF_ST);
    float* ssq = ssum + 128;
    const uint32_t sb = smem_u32(smem);
    const int tid = threadIdx.x, lane = tid & 31, wid = tid >> 5;
    const int wm = wid & 1, wn = wid >> 1;
    const int rowBase = blockIdx.x * 64;
    const int Kw = KC * 128;
    const __half* W = g_Bt16 + btOff;

    if (tid < 128) { ssum[tid] = 0.f; ssq[tid] = 0.f; }

    float acc[2][4][4];
#pragma unroll
    for (int t = 0; t < 2; t++)
#pragma unroll
        for (int nt = 0; nt < 4; nt++)
#pragma unroll
            for (int j = 0; j < 4; j++) acc[t][nt][j] = 0.f;

    // group0: W chunk0; group1 (KC==2): raw fp32 A chunk1 into ARAW
    stage_w_async(W, Kw, 0, sb + OFF_W, tid);
    CP_COMMIT();
    if (KC == 2) {
#pragma unroll
        for (int it = 0; it < 8; it++) {
            int idx = tid + 256 * it;
            int r = idx >> 5;
            int kk = (idx & 31) * 4;
            int row = rowBase + r;
            int srow = (row < n) ? row : 0;  // clamp; zeroed at convert
            cpasync16(sb + OFF_ARAW + (uint32_t)idx * 16u,
                      A + (size_t)srow * Kw + 128 + kk);
        }
        CP_COMMIT();
    }
    stage_act<PRO>(A, Kw, 0, rowBase, n, aH, aL, bnIdx, tid);
    if (KC == 2) CP_WAIT1(); else CP_WAIT0();  // W0 ready (ARAW may still fly)
    __syncthreads();

    gemm_tile_pipe(sb, sb + OFF_AL, sb + OFF_W, acc, wm, wn, lane);

    if (KC == 2) {
        __syncthreads();  // gemm0 reads done -> W buffer reusable
        stage_w_async(W, Kw, 128, sb + OFF_W, tid);
        CP_COMMIT();
        CP_WAIT1();  // ARAW arrived (W1 is the single pending group)
        // convert raw fp32 chunk1 (smem) -> fp16 hi/lo swizzled, in place over aH/aL
#pragma unroll
        for (int it = 0; it < 8; it++) {
            int idx = tid + 256 * it;
            int r = idx >> 5;
            int kk = (idx & 31) * 4;
            float4 v = *(const float4*)(smem + OFF_ARAW + (size_t)idx * 16);
            if (rowBase + r >= n) v = make_float4(0.f, 0.f, 0.f, 0.f);
            v = bn_tf<PRO>(v, 128 + kk, bnIdx);
            split_store(v, r, kk, aH, aL);
        }
        CP_WAIT0();
        __syncthreads();
        gemm_tile_pipe(sb, sb + OFF_AL, sb + OFF_W, acc, wm, wn, lane);
    }

    // epilogue: bias, store fp32, fused column stats
    const int r0 = rowBase + wm * 32 + (lane >> 2);
    const int colb = wn * 32 + (lane & 3) * 2;
#pragma unroll
    for (int nt = 0; nt < 4; nt++) {
        int cc = colb + nt * 8;
        float bx = bias[cc], by = bias[cc + 1];
        float p0 = 0.f, p1 = 0.f, q0 = 0.f, q1 = 0.f;
#pragma unroll
        for (int t = 0; t < 2; t++) {
#pragma unroll
            for (int h = 0; h < 2; h++) {
                int row = r0 + t * 16 + h * 8;
                float y0 = acc[t][nt][h * 2] + bx;
                float y1 = acc[t][nt][h * 2 + 1] + by;
                if (row < n) {
                    *(float2*)(out + (size_t)row * HID + cc) = make_float2(y0, y1);
                    p0 += y0; q0 += y0 * y0;
                    p1 += y1; q1 += y1 * y1;
                }
            }
        }
#pragma unroll
        for (int m = 4; m <= 16; m <<= 1) {
            p0 += __shfl_xor_sync(~0u, p0, m);
            p1 += __shfl_xor_sync(~0u, p1, m);
            q0 += __shfl_xor_sync(~0u, q0, m);
            q1 += __shfl_xor_sync(~0u, q1, m);
        }
        if ((lane >> 2) == 0) {
            atomicAdd(&ssum[cc], p0);
            atomicAdd(&ssum[cc + 1], p1);
            atomicAdd(&ssq[cc], q0);
            atomicAdd(&ssq[cc + 1], q1);
        }
    }
    __syncthreads();
    if (tid < 128) {
        atomicAdd(&g_colsum[tid], ssum[tid]);
        atomicAdd(&g_colsq[tid], ssq[tid]);
    }
}

// ---------------- fused 4-GEMM attention kernel ----------------
// smem: aH(16K) aL(16K) w(32K) = 64KB; regs<=84 -> 3 CTAs/SM
#define FUS_SMEM 65536
__global__ void __launch_bounds__(256, 3)
k_fused(const float* __restrict__ A, const float* __restrict__ bv,
        const float* __restrict__ bo, float* __restrict__ out, int n) {
    extern __shared__ char smem[];
    const uint32_t sb = smem_u32(smem);
    const int tid = threadIdx.x, lane = tid & 31, wid = tid >> 5;
    const int wm = wid & 1, wn = wid >> 1;
    const int rowBase = blockIdx.x * 64;

    const int woffs[4] = {49152, 65536, 81920, 98304};
    const float* biases[4] = {bv, bo, bv + HID, bo + HID};

    // prefetch W0 + initial act stage (BN#1 + relu on y2)
    stage_w_async(g_Bt16 + woffs[0], 128, 0, sb + OFF_W, tid);
    CP_COMMIT();
    stage_act<1>(A, 128, 0, rowBase, n, smem, smem + OFF_AL, 1, tid);
    CP_WAIT0();
    __syncthreads();

    float mk[2][2];
#pragma unroll
    for (int t = 0; t < 2; t++)
#pragma unroll
        for (int h = 0; h < 2; h++) {
            int row = rowBase + wm * 32 + t * 16 + h * 8 + (lane >> 2);
            mk[t][h] = (row < n) ? g_mask[row] : 0.f;
        }

    for (int s = 0; s < 4; s++) {
        float acc[2][4][4];
#pragma unroll
        for (int t = 0; t < 2; t++)
#pragma unroll
            for (int nt = 0; nt < 4; nt++)
#pragma unroll
                for (int j = 0; j < 4; j++) acc[t][nt][j] = 0.f;

        gemm_tile_simple(sb, sb + OFF_AL, sb + OFF_W, acc, wm, wn, lane);
        __syncthreads();  // all reads of act+W done -> safe to overwrite both

        if (s < 3) {
            stage_w_async(g_Bt16 + woffs[s + 1], 128, 0, sb + OFF_W, tid);
            CP_COMMIT();
        }

        const float* bias = biases[s];
        const bool isMask = (s & 1) == 0;
        const bool last = (s == 3);
        const int colb = wn * 32 + (lane & 3) * 2;
#pragma unroll
        for (int nt = 0; nt < 4; nt++) {
            int cc = colb + nt * 8;
            float bx = bias[cc], by = bias[cc + 1];
#pragma unroll
            for (int t = 0; t < 2; t++) {
#pragma unroll
                for (int h = 0; h < 2; h++) {
                    float y0 = acc[t][nt][h * 2] + bx;
                    float y1 = acc[t][nt][h * 2 + 1] + by;
                    if (isMask) {
                        y0 *= mk[t][h];
                        y1 *= mk[t][h];
                    } else {
                        y0 = fmaxf(y0, 0.f);
                        y1 = fmaxf(y1, 0.f);
                    }
                    int rl = wm * 32 + t * 16 + h * 8 + (lane >> 2);
                    if (last) {
                        int row = rowBase + rl;
                        if (row < n)
                            *(float2*)(out + (size_t)row * HID + cc) = make_float2(y0, y1);
                    } else {
                        __half h0 = __float2half_rn(y0);
                        __half h1 = __float2half_rn(y1);
                        uint32_t hi = pack_h2(h0, h1);
                        uint32_t lo = pack_h2(__float2half_rn(y0 - __half2float(h0)),
                                              __float2half_rn(y1 - __half2float(h1)));
                        uint32_t so = swzb(rl, cc * 2);
                        *(uint32_t*)(smem + so) = hi;
                        *(uint32_t*)(smem + OFF_AL + so) = lo;
                    }
                }
            }
        }
        if (!last) {
            CP_WAIT0();
            __syncthreads();  // epilogue visible + next weights ready
        }
    }
}

// ---------------- launch ----------------
extern "C" void kernel_launch(void* const* d_in, const int* in_sizes, int n_in,
                              void* d_out, int out_size) {
    const float* x   = (const float*)d_in[0];
    const int*   ei  = (const int*)d_in[1];
    const float* W1  = (const float*)d_in[2];
    const float* b1  = (const float*)d_in[3];
    const float* g1  = (const float*)d_in[4];
    const float* be1 = (const float*)d_in[5];
    const float* W2  = (const float*)d_in[6];
    const float* b2  = (const float*)d_in[7];
    const float* g2  = (const float*)d_in[8];
    const float* be2 = (const float*)d_in[9];
    // d_in[10..13] = Wq,bq,Wk,bk : mathematically unused (softmax over dst sums to 1)
    const float* Wv  = (const float*)d_in[14];
    const float* bv  = (const float*)d_in[15];
    const float* Wo  = (const float*)d_in[16];
    const float* bo  = (const float*)d_in[17];
    float* out = (float*)d_out;

    const int n = in_sizes[0] / 256;
    const int E = in_sizes[1] / 2;
    const int* dst = ei + E;

    float *bufA, *bufB, *mask;
    cudaGetSymbolAddress((void**)&bufA, g_bufA);
    cudaGetSymbolAddress((void**)&bufB, g_bufB);
    cudaGetSymbolAddress((void**)&mask, g_mask);

    cudaFuncSetAttribute(k_enc<2, 0>, cudaFuncAttributeMaxDynamicSharedMemorySize, ENC_SMEM);
    cudaFuncSetAttribute(k_enc<1, 1>, cudaFuncAttributeMaxDynamicSharedMemorySize, ENC_SMEM);
    cudaFuncSetAttribute(k_fused, cudaFuncAttributeMaxDynamicSharedMemorySize, FUS_SMEM);

    const int gblk = (n + 63) / 64;

    k_prep<<<dim3(128, 6), 256>>>(W1, W2, Wv, Wo);
    k_init<<<(n + 255) / 256, 256>>>(mask, n);
    k_scatter<<<(E + 255) / 256, 256>>>(dst, E, mask);

    // encoder layer 1: y1 = x @ W1 + b1 (stats fused) -> BN #0
    k_enc<2, 0><<<gblk, 256, ENC_SMEM>>>(x, 0, b1, bufA, n, 0);
    k_finalize<<<1, 128>>>(g1, be1, 0, n);

    // encoder layer 2: y2 = relu(bn0(y1)) @ W2 + b2 (stats fused) -> BN #1
    k_enc<1, 1><<<gblk, 256, ENC_SMEM>>>(bufA, 32768, b2, bufB, n, 0);
    k_finalize<<<1, 128>>>(g2, be2, 1, n);

    // fused attention stack (Wv0/mask -> Wo0/relu -> Wv1/mask -> Wo1/relu)
    k_fused<<<gblk, 256, FUS_SMEM>>>(bufB, bv, bo, out, n);
}

// round 15
// speedup vs baseline: 1.3323x; 1.2493x over previous
#include <cuda_runtime.h>
#include <cuda_bf16.h>
#include <cuda_fp16.h>
#include <cstdint>

#define NMAX 50000
#define HID 128

// ---------------- scratch ----------------
__device__ __align__(16) float g_bufA[NMAX * HID];
__device__ __align__(16) float g_bufB[NMAX * HID];
__device__ float g_mask[NMAX];
__device__ float g_colsum[HID];
__device__ float g_colsq[HID];
__device__ float g_bnscale[2][HID];
__device__ float g_bnshift[2][HID];
// transposed weights ([n][k] fp16, single rounded copy): W1T(128x256) then 5x(128x128)
__device__ __align__(16) __half g_Bt16[32768 + 5 * 16384];

// ---------------- helpers ----------------
__device__ __forceinline__ uint32_t smem_u32(const void* p) {
    uint32_t a;
    asm("{ .reg .u64 t; cvta.to.shared.u64 t, %1; cvt.u32.u64 %0, t; }"
        : "=r"(a) : "l"(p));
    return a;
}
__device__ __forceinline__ void ldsm4(uint32_t* r, uint32_t addr) {
    asm volatile("ldmatrix.sync.aligned.m8n8.x4.shared.b16 {%0,%1,%2,%3}, [%4];"
                 : "=r"(r[0]), "=r"(r[1]), "=r"(r[2]), "=r"(r[3]) : "r"(addr));
}
__device__ __forceinline__ void mma16816(float* c, const uint32_t* a, const uint32_t* b) {
    asm volatile(
        "mma.sync.aligned.m16n8k16.row.col.f32.f16.f16.f32 "
        "{%0,%1,%2,%3}, {%4,%5,%6,%7}, {%8,%9}, {%0,%1,%2,%3};"
        : "+f"(c[0]), "+f"(c[1]), "+f"(c[2]), "+f"(c[3])
        : "r"(a[0]), "r"(a[1]), "r"(a[2]), "r"(a[3]), "r"(b[0]), "r"(b[1]));
}
__device__ __forceinline__ void cpasync16(uint32_t dst, const void* src) {
    asm volatile("cp.async.cg.shared.global [%0], [%1], 16;" :: "r"(dst), "l"(src));
}
#define CP_COMMIT() asm volatile("cp.async.commit_group;" ::: "memory")
#define CP_WAIT0() asm volatile("cp.async.wait_group 0;" ::: "memory")
#define CP_WAIT1() asm volatile("cp.async.wait_group 1;" ::: "memory")

__device__ __forceinline__ uint32_t pack_h2(__half a, __half b) {
    return ((uint32_t)__half_as_ushort(b) << 16) | (uint32_t)__half_as_ushort(a);
}
// XOR-swizzled offset inside a tile with 256B row stride (128 fp16 cols)
__device__ __forceinline__ uint32_t swzb(int r, int kbyte) {
    return (uint32_t)r * 256u + (uint32_t)(kbyte ^ ((r & 7) << 4));
}

// ---------------- small kernels ----------------
__global__ void k_init(float* mask, int n) {
    int i = blockIdx.x * blockDim.x + threadIdx.x;
    if (i < n) mask[i] = 0.f;
    if (i < HID) { g_colsum[i] = 0.f; g_colsq[i] = 0.f; }
}
__global__ void k_scatter(const int* __restrict__ dst, int E, float* __restrict__ mask) {
    int e = blockIdx.x * blockDim.x + threadIdx.x;
    if (e < E) mask[dst[e]] = 1.0f;
}
__global__ void k_finalize(const float* __restrict__ g, const float* __restrict__ beta,
                           int idx, int n) {
    int c = threadIdx.x;
    float inv = 1.0f / (float)n;
    float mean = g_colsum[c] * inv;
    float var = g_colsq[c] * inv - mean * mean;
    float sc = g[c] * rsqrtf(var + 1e-5f);
    g_bnscale[idx][c] = sc;
    g_bnshift[idx][c] = beta[c] - sc * mean;
    g_colsum[c] = 0.f;
    g_colsq[c] = 0.f;
}
// transpose weights into [n][k] fp16 (single rounded copy)
__global__ void k_prep(const float* __restrict__ W1, const float* __restrict__ W2,
                       const float* __restrict__ Wv, const float* __restrict__ Wo) {
    int m = blockIdx.y;
    const float* src; int K, off;
    switch (m) {
        case 0: src = W1; K = 256; off = 0; break;
        case 1: src = W2; K = 128; off = 32768; break;
        case 2: src = Wv; K = 128; off = 49152; break;
        case 3: src = Wo; K = 128; off = 65536; break;
        case 4: src = Wv + 16384; K = 128; off = 81920; break;
        default: src = Wo + 16384; K = 128; off = 98304; break;
    }
    int idx = blockIdx.x * 256 + threadIdx.x;
    if (idx < K * 128) {
        int k = idx >> 7, nn = idx & 127;
        g_Bt16[off + nn * K + k] = __float2half_rn(src[idx]);
    }
}

// ---------------- staging (256 threads, 64-row act tiles, single fp16) ----------
__device__ __forceinline__ void store_h(float4 v, int r, int kk, char* dA) {
    __half h0 = __float2half_rn(v.x), h1 = __float2half_rn(v.y);
    __half h2 = __float2half_rn(v.z), h3 = __float2half_rn(v.w);
    uint32_t so = swzb(r, kk * 2);
    *(uint2*)(dA + so) = make_uint2(pack_h2(h0, h1), pack_h2(h2, h3));
}
template <int PRO>
__device__ __forceinline__ float4 bn_tf(float4 v, int gk, int bnIdx) {
    if (PRO) {
        const float* sc = g_bnscale[bnIdx];
        const float* sh = g_bnshift[bnIdx];
        v.x = fmaxf(fmaf(sc[gk + 0], v.x, sh[gk + 0]), 0.f);
        v.y = fmaxf(fmaf(sc[gk + 1], v.y, sh[gk + 1]), 0.f);
        v.z = fmaxf(fmaf(sc[gk + 2], v.z, sh[gk + 2]), 0.f);
        v.w = fmaxf(fmaf(sc[gk + 3], v.w, sh[gk + 3]), 0.f);
    }
    return v;
}
// 64 rows x 128 cols fp32 -> fp16 swizzled (256 threads)
template <int PRO>
__device__ __forceinline__ void stage_act(const float* __restrict__ A, int Kld, int kcol0,
                                          int rowBase, int n, char* dA, int bnIdx,
                                          int tid) {
#pragma unroll
    for (int it = 0; it < 8; it++) {
        int f4 = tid + 256 * it;
        int r = f4 >> 5;
        int kk = (f4 & 31) * 4;
        int row = rowBase + r;
        float4 v = make_float4(0.f, 0.f, 0.f, 0.f);
        if (row < n) v = *(const float4*)(A + (size_t)row * Kld + kcol0 + kk);
        v = bn_tf<PRO>(v, kcol0 + kk, bnIdx);
        store_h(v, r, kk, dA);
    }
}
// async weight stage: full 128n x 128k fp16 chunk (32KB) via cp.async
__device__ __forceinline__ void stage_w_async(const __half* __restrict__ W, int Kw,
                                              int k0, uint32_t dW, int tid) {
#pragma unroll
    for (int it = 0; it < 8; it++) {
        int idx = tid + 256 * it;
        int nr = idx >> 4;
        int kg = (idx & 15) * 16;
        uint32_t so = swzb(nr, kg);
        cpasync16(dW + so, (const char*)W + (size_t)nr * Kw * 2 + k0 * 2 + kg);
    }
}

// ---------------- warp GEMM: 32x32 per warp, 2x4 warp grid, single pass ----------
__device__ __forceinline__ void gemm_tile_simple(uint32_t sA, uint32_t sW,
                                                 float acc[2][4][4], int wm, int wn,
                                                 int lane) {
    const uint32_t aBase = (uint32_t)(wm * 32 + (lane & 15)) * 256u;
    const uint32_t aXor = (uint32_t)(((wm * 32 + (lane & 15)) & 7) << 4);
    const int aKb = (lane >> 4) * 16;
    const int nB = wn * 32 + (lane & 7) + ((lane & 16) ? 8 : 0);
    const uint32_t bBase = (uint32_t)nB * 256u;
    const uint32_t bXor = (uint32_t)((nB & 7) << 4);
    const int bKb = (lane & 8) ? 16 : 0;

#pragma unroll
    for (int ks = 0; ks < 8; ks++) {
        const int kb = ks * 32;
        uint32_t Ah[2][4], Bh[2][4];
#pragma unroll
        for (int t = 0; t < 2; t++) {
            uint32_t off = aBase + (uint32_t)t * 4096u + (uint32_t)((kb + aKb) ^ (int)aXor);
            ldsm4(Ah[t], sA + off);
        }
#pragma unroll
        for (int g = 0; g < 2; g++) {
            uint32_t off = bBase + (uint32_t)g * 4096u + (uint32_t)((kb + bKb) ^ (int)bXor);
            ldsm4(Bh[g], sW + off);
        }
#pragma unroll
        for (int t = 0; t < 2; t++)
#pragma unroll
            for (int nt = 0; nt < 4; nt++)
                mma16816(acc[t][nt], Ah[t], &Bh[nt >> 1][(nt & 1) * 2]);
    }
}
// pipelined variant: double-buffered LDSM fragments
__device__ __forceinline__ void gemm_tile_pipe(uint32_t sA, uint32_t sW,
                                               float acc[2][4][4], int wm, int wn,
                                               int lane) {
    const uint32_t aBase = (uint32_t)(wm * 32 + (lane & 15)) * 256u;
    const uint32_t aXor = (uint32_t)(((wm * 32 + (lane & 15)) & 7) << 4);
    const int aKb = (lane >> 4) * 16;
    const int nB = wn * 32 + (lane & 7) + ((lane & 16) ? 8 : 0);
    const uint32_t bBase = (uint32_t)nB * 256u;
    const uint32_t bXor = (uint32_t)((nB & 7) << 4);
    const int bKb = (lane & 8) ? 16 : 0;

    uint32_t Ah[2][2][4], Bh[2][2][4];

    auto loadf = [&](int ks, int buf) {
        const int kb = ks * 32;
#pragma unroll
        for (int t = 0; t < 2; t++) {
            uint32_t off = aBase + (uint32_t)t * 4096u + (uint32_t)((kb + aKb) ^ (int)aXor);
            ldsm4(Ah[buf][t], sA + off);
        }
#pragma unroll
        for (int g = 0; g < 2; g++) {
            uint32_t off = bBase + (uint32_t)g * 4096u + (uint32_t)((kb + bKb) ^ (int)bXor);
            ldsm4(Bh[buf][g], sW + off);
        }
    };

    loadf(0, 0);
#pragma unroll
    for (int ks = 0; ks < 8; ks++) {
        const int cur = ks & 1;
        if (ks < 7) loadf(ks + 1, cur ^ 1);  // prefetch next fragments under MMAs
#pragma unroll
        for (int t = 0; t < 2; t++)
#pragma unroll
            for (int nt = 0; nt < 4; nt++)
                mma16816(acc[t][nt], Ah[cur][t], &Bh[cur][nt >> 1][(nt & 1) * 2]);
    }
}

// ---------------- encoder GEMM kernel (fp32 out + fused BN stats) ----------------
// smem: a(16K) w(32K) araw(32K) stats(1K) = 81KB -> 2 CTAs/SM
#define OFF_W 16384
#define OFF_ARAW 49152
#define OFF_ST 81920
#define ENC_SMEM (81920 + 1024)
template <int KC, int PRO>
__global__ void __launch_bounds__(256, 2)
k_enc(const float* __restrict__ A, int btOff, const float* __restrict__ bias,
      float* __restrict__ out, int n, int bnIdx) {
    extern __shared__ char smem[];
    char* aA = smem;
    float* ssum = (float*)(smem + OFF_ST);
    float* ssq = ssum + 128;
    const uint32_t sb = smem_u32(smem);
    const int tid = threadIdx.x, lane = tid & 31, wid = tid >> 5;
    const int wm = wid & 1, wn = wid >> 1;
    const int rowBase = blockIdx.x * 64;
    const int Kw = KC * 128;
    const __half* W = g_Bt16 + btOff;

    if (tid < 128) { ssum[tid] = 0.f; ssq[tid] = 0.f; }

    float acc[2][4][4];
#pragma unroll
    for (int t = 0; t < 2; t++)
#pragma unroll
        for (int nt = 0; nt < 4; nt++)
#pragma unroll
            for (int j = 0; j < 4; j++) acc[t][nt][j] = 0.f;

    // group0: W chunk0; group1 (KC==2): raw fp32 A chunk1 into ARAW
    stage_w_async(W, Kw, 0, sb + OFF_W, tid);
    CP_COMMIT();
    if (KC == 2) {
#pragma unroll
        for (int it = 0; it < 8; it++) {
            int idx = tid + 256 * it;
            int r = idx >> 5;
            int kk = (idx & 31) * 4;
            int row = rowBase + r;
            int srow = (row < n) ? row : 0;  // clamp; zeroed at convert
            cpasync16(sb + OFF_ARAW + (uint32_t)idx * 16u,
                      A + (size_t)srow * Kw + 128 + kk);
        }
        CP_COMMIT();
    }
    stage_act<PRO>(A, Kw, 0, rowBase, n, aA, bnIdx, tid);
    if (KC == 2) CP_WAIT1(); else CP_WAIT0();  // W0 ready (ARAW may still fly)
    __syncthreads();

    gemm_tile_pipe(sb, sb + OFF_W, acc, wm, wn, lane);

    if (KC == 2) {
        __syncthreads();  // gemm0 reads done -> W buffer reusable
        stage_w_async(W, Kw, 128, sb + OFF_W, tid);
        CP_COMMIT();
        CP_WAIT1();  // ARAW arrived (W1 is the single pending group)
        // convert raw fp32 chunk1 (smem) -> fp16 swizzled, in place over aA
#pragma unroll
        for (int it = 0; it < 8; it++) {
            int idx = tid + 256 * it;
            int r = idx >> 5;
            int kk = (idx & 31) * 4;
            float4 v = *(const float4*)(smem + OFF_ARAW + (size_t)idx * 16);
            if (rowBase + r >= n) v = make_float4(0.f, 0.f, 0.f, 0.f);
            v = bn_tf<PRO>(v, 128 + kk, bnIdx);
            store_h(v, r, kk, aA);
        }
        CP_WAIT0();
        __syncthreads();
        gemm_tile_pipe(sb, sb + OFF_W, acc, wm, wn, lane);
    }

    // epilogue: bias, store fp32, fused column stats
    const int r0 = rowBase + wm * 32 + (lane >> 2);
    const int colb = wn * 32 + (lane & 3) * 2;
#pragma unroll
    for (int nt = 0; nt < 4; nt++) {
        int cc = colb + nt * 8;
        float bx = bias[cc], by = bias[cc + 1];
        float p0 = 0.f, p1 = 0.f, q0 = 0.f, q1 = 0.f;
#pragma unroll
        for (int t = 0; t < 2; t++) {
#pragma unroll
            for (int h = 0; h < 2; h++) {
                int row = r0 + t * 16 + h * 8;
                float y0 = acc[t][nt][h * 2] + bx;
                float y1 = acc[t][nt][h * 2 + 1] + by;
                if (row < n) {
                    *(float2*)(out + (size_t)row * HID + cc) = make_float2(y0, y1);
                    p0 += y0; q0 += y0 * y0;
                    p1 += y1; q1 += y1 * y1;
                }
            }
        }
#pragma unroll
        for (int m = 4; m <= 16; m <<= 1) {
            p0 += __shfl_xor_sync(~0u, p0, m);
            p1 += __shfl_xor_sync(~0u, p1, m);
            q0 += __shfl_xor_sync(~0u, q0, m);
            q1 += __shfl_xor_sync(~0u, q1, m);
        }
        if ((lane >> 2) == 0) {
            atomicAdd(&ssum[cc], p0);
            atomicAdd(&ssum[cc + 1], p1);
            atomicAdd(&ssq[cc], q0);
            atomicAdd(&ssq[cc + 1], q1);
        }
    }
    __syncthreads();
    if (tid < 128) {
        atomicAdd(&g_colsum[tid], ssum[tid]);
        atomicAdd(&g_colsq[tid], ssq[tid]);
    }
}

// ---------------- fused 4-GEMM attention kernel ----------------
// smem: a(16K) w(32K) = 48KB; regs<=84 -> 3 CTAs/SM
#define FUS_SMEM 49152
__global__ void __launch_bounds__(256, 3)
k_fused(const float* __restrict__ A, const float* __restrict__ bv,
        const float* __restrict__ bo, float* __restrict__ out, int n) {
    extern __shared__ char smem[];
    const uint32_t sb = smem_u32(smem);
    const int tid = threadIdx.x, lane = tid & 31, wid = tid >> 5;
    const int wm = wid & 1, wn = wid >> 1;
    const int rowBase = blockIdx.x * 64;

    const int woffs[4] = {49152, 65536, 81920, 98304};
    const float* biases[4] = {bv, bo, bv + HID, bo + HID};

    // prefetch W0 + initial act stage (BN#1 + relu on y2)
    stage_w_async(g_Bt16 + woffs[0], 128, 0, sb + OFF_W, tid);
    CP_COMMIT();
    stage_act<1>(A, 128, 0, rowBase, n, smem, 1, tid);
    CP_WAIT0();
    __syncthreads();

    float mk[2][2];
#pragma unroll
    for (int t = 0; t < 2; t++)
#pragma unroll
        for (int h = 0; h < 2; h++) {
            int row = rowBase + wm * 32 + t * 16 + h * 8 + (lane >> 2);
            mk[t][h] = (row < n) ? g_mask[row] : 0.f;
        }

    for (int s = 0; s < 4; s++) {
        float acc[2][4][4];
#pragma unroll
        for (int t = 0; t < 2; t++)
#pragma unroll
            for (int nt = 0; nt < 4; nt++)
#pragma unroll
                for (int j = 0; j < 4; j++) acc[t][nt][j] = 0.f;

        gemm_tile_simple(sb, sb + OFF_W, acc, wm, wn, lane);
        __syncthreads();  // all reads of act+W done -> safe to overwrite both

        if (s < 3) {
            stage_w_async(g_Bt16 + woffs[s + 1], 128, 0, sb + OFF_W, tid);
            CP_COMMIT();
        }

        const float* bias = biases[s];
        const bool isMask = (s & 1) == 0;
        const bool last = (s == 3);
        const int colb = wn * 32 + (lane & 3) * 2;
#pragma unroll
        for (int nt = 0; nt < 4; nt++) {
            int cc = colb + nt * 8;
            float bx = bias[cc], by = bias[cc + 1];
#pragma unroll
            for (int t = 0; t < 2; t++) {
#pragma unroll
                for (int h = 0; h < 2; h++) {
                    float y0 = acc[t][nt][h * 2] + bx;
                    float y1 = acc[t][nt][h * 2 + 1] + by;
                    if (isMask) {
                        y0 *= mk[t][h];
                        y1 *= mk[t][h];
                    } else {
                        y0 = fmaxf(y0, 0.f);
                        y1 = fmaxf(y1, 0.f);
                    }
                    int rl = wm * 32 + t * 16 + h * 8 + (lane >> 2);
                    if (last) {
                        int row = rowBase + rl;
                        if (row < n)
                            *(float2*)(out + (size_t)row * HID + cc) = make_float2(y0, y1);
                    } else {
                        uint32_t hi = pack_h2(__float2half_rn(y0), __float2half_rn(y1));
                        *(uint32_t*)(smem + swzb(rl, cc * 2)) = hi;
                    }
                }
            }
        }
        if (!last) {
            CP_WAIT0();
            __syncthreads();  // epilogue visible + next weights ready
        }
    }
}

// ---------------- launch ----------------
extern "C" void kernel_launch(void* const* d_in, const int* in_sizes, int n_in,
                              void* d_out, int out_size) {
    const float* x   = (const float*)d_in[0];
    const int*   ei  = (const int*)d_in[1];
    const float* W1  = (const float*)d_in[2];
    const float* b1  = (const float*)d_in[3];
    const float* g1  = (const float*)d_in[4];
    const float* be1 = (const float*)d_in[5];
    const float* W2  = (const float*)d_in[6];
    const float* b2  = (const float*)d_in[7];
    const float* g2  = (const float*)d_in[8];
    const float* be2 = (const float*)d_in[9];
    // d_in[10..13] = Wq,bq,Wk,bk : mathematically unused (softmax over dst sums to 1)
    const float* Wv  = (const float*)d_in[14];
    const float* bv  = (const float*)d_in[15];
    const float* Wo  = (const float*)d_in[16];
    const float* bo  = (const float*)d_in[17];
    float* out = (float*)d_out;

    const int n = in_sizes[0] / 256;
    const int E = in_sizes[1] / 2;
    const int* dst = ei + E;

    float *bufA, *bufB, *mask;
    cudaGetSymbolAddress((void**)&bufA, g_bufA);
    cudaGetSymbolAddress((void**)&bufB, g_bufB);
    cudaGetSymbolAddress((void**)&mask, g_mask);

    cudaFuncSetAttribute(k_enc<2, 0>, cudaFuncAttributeMaxDynamicSharedMemorySize, ENC_SMEM);
    cudaFuncSetAttribute(k_enc<1, 1>, cudaFuncAttributeMaxDynamicSharedMemorySize, ENC_SMEM);
    cudaFuncSetAttribute(k_fused, cudaFuncAttributeMaxDynamicSharedMemorySize, FUS_SMEM);

    const int gblk = (n + 63) / 64;

    k_prep<<<dim3(128, 6), 256>>>(W1, W2, Wv, Wo);
    k_init<<<(n + 255) / 256, 256>>>(mask, n);
    k_scatter<<<(E + 255) / 256, 256>>>(dst, E, mask);

    // encoder layer 1: y1 = x @ W1 + b1 (stats fused) -> BN #0
    k_enc<2, 0><<<gblk, 256, ENC_SMEM>>>(x, 0, b1, bufA, n, 0);
    k_finalize<<<1, 128>>>(g1, be1, 0, n);

    // encoder layer 2: y2 = relu(bn0(y1)) @ W2 + b2 (stats fused) -> BN #1
    k_enc<1, 1><<<gblk, 256, ENC_SMEM>>>(bufA, 32768, b2, bufB, n, 0);
    k_finalize<<<1, 128>>>(g2, be2, 1, n);

    // fused attention stack (Wv0/mask -> Wo0/relu -> Wv1/mask -> Wo1/relu)
    k_fused<<<gblk, 256, FUS_SMEM>>>(bufB, bv, bo, out, n);
}

// round 16
// speedup vs baseline: 1.3611x; 1.0216x over previous
#include <cuda_runtime.h>
#include <cuda_bf16.h>
#include <cuda_fp16.h>
#include <cstdint>

#define NMAX 50000
#define HID 128

// ---------------- scratch ----------------
__device__ __align__(16) __half g_hbufA[NMAX * HID];  // y1 (fp16)
__device__ __align__(16) __half g_hbufB[NMAX * HID];  // y2 (fp16)
__device__ float g_mask[NMAX];
__device__ float g_colsum[HID];
__device__ float g_colsq[HID];
__device__ float g_bnscale[2][HID];
__device__ float g_bnshift[2][HID];
// transposed weights ([n][k] fp16, single rounded copy): W1T(128x256) then 5x(128x128)
__device__ __align__(16) __half g_Bt16[32768 + 5 * 16384];

// ---------------- helpers ----------------
__device__ __forceinline__ uint32_t smem_u32(const void* p) {
    uint32_t a;
    asm("{ .reg .u64 t; cvta.to.shared.u64 t, %1; cvt.u32.u64 %0, t; }"
        : "=r"(a) : "l"(p));
    return a;
}
__device__ __forceinline__ void ldsm4(uint32_t* r, uint32_t addr) {
    asm volatile("ldmatrix.sync.aligned.m8n8.x4.shared.b16 {%0,%1,%2,%3}, [%4];"
                 : "=r"(r[0]), "=r"(r[1]), "=r"(r[2]), "=r"(r[3]) : "r"(addr));
}
__device__ __forceinline__ void mma16816(float* c, const uint32_t* a, const uint32_t* b) {
    asm volatile(
        "mma.sync.aligned.m16n8k16.row.col.f32.f16.f16.f32 "
        "{%0,%1,%2,%3}, {%4,%5,%6,%7}, {%8,%9}, {%0,%1,%2,%3};"
        : "+f"(c[0]), "+f"(c[1]), "+f"(c[2]), "+f"(c[3])
        : "r"(a[0]), "r"(a[1]), "r"(a[2]), "r"(a[3]), "r"(b[0]), "r"(b[1]));
}
__device__ __forceinline__ void cpasync16(uint32_t dst, const void* src) {
    asm volatile("cp.async.cg.shared.global [%0], [%1], 16;" :: "r"(dst), "l"(src));
}
#define CP_COMMIT() asm volatile("cp.async.commit_group;" ::: "memory")
#define CP_WAIT0() asm volatile("cp.async.wait_group 0;" ::: "memory")
#define CP_WAIT1() asm volatile("cp.async.wait_group 1;" ::: "memory")

__device__ __forceinline__ uint32_t pack_h2(__half a, __half b) {
    return ((uint32_t)__half_as_ushort(b) << 16) | (uint32_t)__half_as_ushort(a);
}
// XOR-swizzled offset inside a tile with 256B row stride (128 fp16 cols)
__device__ __forceinline__ uint32_t swzb(int r, int kbyte) {
    return (uint32_t)r * 256u + (uint32_t)(kbyte ^ ((r & 7) << 4));
}

// ---------------- small kernels ----------------
__global__ void k_init(float* mask, int n) {
    int i = blockIdx.x * blockDim.x + threadIdx.x;
    if (i < n) mask[i] = 0.f;
    if (i < HID) { g_colsum[i] = 0.f; g_colsq[i] = 0.f; }
}
__global__ void k_scatter(const int* __restrict__ dst, int E, float* __restrict__ mask) {
    int e = blockIdx.x * blockDim.x + threadIdx.x;
    if (e < E) mask[dst[e]] = 1.0f;
}
__global__ void k_finalize(const float* __restrict__ g, const float* __restrict__ beta,
                           int idx, int n) {
    int c = threadIdx.x;
    float inv = 1.0f / (float)n;
    float mean = g_colsum[c] * inv;
    float var = g_colsq[c] * inv - mean * mean;
    float sc = g[c] * rsqrtf(var + 1e-5f);
    g_bnscale[idx][c] = sc;
    g_bnshift[idx][c] = beta[c] - sc * mean;
    g_colsum[c] = 0.f;
    g_colsq[c] = 0.f;
}
// transpose weights into [n][k] fp16 (single rounded copy)
__global__ void k_prep(const float* __restrict__ W1, const float* __restrict__ W2,
                       const float* __restrict__ Wv, const float* __restrict__ Wo) {
    int m = blockIdx.y;
    const float* src; int K, off;
    switch (m) {
        case 0: src = W1; K = 256; off = 0; break;
        case 1: src = W2; K = 128; off = 32768; break;
        case 2: src = Wv; K = 128; off = 49152; break;
        case 3: src = Wo; K = 128; off = 65536; break;
        case 4: src = Wv + 16384; K = 128; off = 81920; break;
        default: src = Wo + 16384; K = 128; off = 98304; break;
    }
    int idx = blockIdx.x * 256 + threadIdx.x;
    if (idx < K * 128) {
        int k = idx >> 7, nn = idx & 127;
        g_Bt16[off + nn * K + k] = __float2half_rn(src[idx]);
    }
}

// ---------------- staging (256 threads, 64-row act tiles, single fp16) ----------
__device__ __forceinline__ void store_h(float4 v, int r, int kk, char* dA) {
    __half h0 = __float2half_rn(v.x), h1 = __float2half_rn(v.y);
    __half h2 = __float2half_rn(v.z), h3 = __float2half_rn(v.w);
    uint32_t so = swzb(r, kk * 2);
    *(uint2*)(dA + so) = make_uint2(pack_h2(h0, h1), pack_h2(h2, h3));
}
template <int PRO>
__device__ __forceinline__ float4 bn_tf(float4 v, int gk, int bnIdx) {
    if (PRO) {
        const float* sc = g_bnscale[bnIdx];
        const float* sh = g_bnshift[bnIdx];
        v.x = fmaxf(fmaf(sc[gk + 0], v.x, sh[gk + 0]), 0.f);
        v.y = fmaxf(fmaf(sc[gk + 1], v.y, sh[gk + 1]), 0.f);
        v.z = fmaxf(fmaf(sc[gk + 2], v.z, sh[gk + 2]), 0.f);
        v.w = fmaxf(fmaf(sc[gk + 3], v.w, sh[gk + 3]), 0.f);
    }
    return v;
}
// 64 rows x 128 cols fp32 -> fp16 swizzled (256 threads)
template <int PRO>
__device__ __forceinline__ void stage_act(const float* __restrict__ A, int Kld, int kcol0,
                                          int rowBase, int n, char* dA, int bnIdx,
                                          int tid) {
#pragma unroll
    for (int it = 0; it < 8; it++) {
        int f4 = tid + 256 * it;
        int r = f4 >> 5;
        int kk = (f4 & 31) * 4;
        int row = rowBase + r;
        float4 v = make_float4(0.f, 0.f, 0.f, 0.f);
        if (row < n) v = *(const float4*)(A + (size_t)row * Kld + kcol0 + kk);
        v = bn_tf<PRO>(v, kcol0 + kk, bnIdx);
        store_h(v, r, kk, dA);
    }
}
// 64 rows x 128 cols fp16(global) -> BN in fp32 -> fp16 swizzled (256 threads)
template <int PRO>
__device__ __forceinline__ void stage_act16(const __half* __restrict__ A, int Kld,
                                            int rowBase, int n, char* dA, int bnIdx,
                                            int tid) {
#pragma unroll
    for (int it = 0; it < 8; it++) {
        int f4 = tid + 256 * it;
        int r = f4 >> 5;
        int kk = (f4 & 31) * 4;
        int row = rowBase + r;
        float4 v = make_float4(0.f, 0.f, 0.f, 0.f);
        if (row < n) {
            uint2 u = *(const uint2*)(A + (size_t)row * Kld + kk);
            __half2 p0 = *reinterpret_cast<__half2*>(&u.x);
            __half2 p1 = *reinterpret_cast<__half2*>(&u.y);
            float2 f0 = __half22float2(p0), f1 = __half22float2(p1);
            v = make_float4(f0.x, f0.y, f1.x, f1.y);
        }
        v = bn_tf<PRO>(v, kk, bnIdx);
        store_h(v, r, kk, dA);
    }
}
// async weight stage: full 128n x 128k fp16 chunk (32KB) via cp.async
__device__ __forceinline__ void stage_w_async(const __half* __restrict__ W, int Kw,
                                              int k0, uint32_t dW, int tid) {
#pragma unroll
    for (int it = 0; it < 8; it++) {
        int idx = tid + 256 * it;
        int nr = idx >> 4;
        int kg = (idx & 15) * 16;
        uint32_t so = swzb(nr, kg);
        cpasync16(dW + so, (const char*)W + (size_t)nr * Kw * 2 + k0 * 2 + kg);
    }
}

// ---------------- warp GEMM: 32x32 per warp, 2x4 warp grid, single pass ----------
__device__ __forceinline__ void gemm_tile_simple(uint32_t sA, uint32_t sW,
                                                 float acc[2][4][4], int wm, int wn,
                                                 int lane) {
    const uint32_t aBase = (uint32_t)(wm * 32 + (lane & 15)) * 256u;
    const uint32_t aXor = (uint32_t)(((wm * 32 + (lane & 15)) & 7) << 4);
    const int aKb = (lane >> 4) * 16;
    const int nB = wn * 32 + (lane & 7) + ((lane & 16) ? 8 : 0);
    const uint32_t bBase = (uint32_t)nB * 256u;
    const uint32_t bXor = (uint32_t)((nB & 7) << 4);
    const int bKb = (lane & 8) ? 16 : 0;

#pragma unroll
    for (int ks = 0; ks < 8; ks++) {
        const int kb = ks * 32;
        uint32_t Ah[2][4], Bh[2][4];
#pragma unroll
        for (int t = 0; t < 2; t++) {
            uint32_t off = aBase + (uint32_t)t * 4096u + (uint32_t)((kb + aKb) ^ (int)aXor);
            ldsm4(Ah[t], sA + off);
        }
#pragma unroll
        for (int g = 0; g < 2; g++) {
            uint32_t off = bBase + (uint32_t)g * 4096u + (uint32_t)((kb + bKb) ^ (int)bXor);
            ldsm4(Bh[g], sW + off);
        }
#pragma unroll
        for (int t = 0; t < 2; t++)
#pragma unroll
            for (int nt = 0; nt < 4; nt++)
                mma16816(acc[t][nt], Ah[t], &Bh[nt >> 1][(nt & 1) * 2]);
    }
}
// pipelined variant: double-buffered LDSM fragments
__device__ __forceinline__ void gemm_tile_pipe(uint32_t sA, uint32_t sW,
                                               float acc[2][4][4], int wm, int wn,
                                               int lane) {
    const uint32_t aBase = (uint32_t)(wm * 32 + (lane & 15)) * 256u;
    const uint32_t aXor = (uint32_t)(((wm * 32 + (lane & 15)) & 7) << 4);
    const int aKb = (lane >> 4) * 16;
    const int nB = wn * 32 + (lane & 7) + ((lane & 16) ? 8 : 0);
    const uint32_t bBase = (uint32_t)nB * 256u;
    const uint32_t bXor = (uint32_t)((nB & 7) << 4);
    const int bKb = (lane & 8) ? 16 : 0;

    uint32_t Ah[2][2][4], Bh[2][2][4];

    auto loadf = [&](int ks, int buf) {
        const int kb = ks * 32;
#pragma unroll
        for (int t = 0; t < 2; t++) {
            uint32_t off = aBase + (uint32_t)t * 4096u + (uint32_t)((kb + aKb) ^ (int)aXor);
            ldsm4(Ah[buf][t], sA + off);
        }
#pragma unroll
        for (int g = 0; g < 2; g++) {
            uint32_t off = bBase + (uint32_t)g * 4096u + (uint32_t)((kb + bKb) ^ (int)bXor);
            ldsm4(Bh[buf][g], sW + off);
        }
    };

    loadf(0, 0);
#pragma unroll
    for (int ks = 0; ks < 8; ks++) {
        const int cur = ks & 1;
        if (ks < 7) loadf(ks + 1, cur ^ 1);  // prefetch next fragments under MMAs
#pragma unroll
        for (int t = 0; t < 2; t++)
#pragma unroll
            for (int nt = 0; nt < 4; nt++)
                mma16816(acc[t][nt], Ah[cur][t], &Bh[cur][nt >> 1][(nt & 1) * 2]);
    }
}

// shared epilogue: bias, fp16 store, fused BN column stats
__device__ __forceinline__ void enc_epilogue(float acc[2][4][4], const float* bias,
                                             __half* out, int n, int rowBase, int wm,
                                             int wn, int lane, int tid, float* ssum,
                                             float* ssq) {
    const int r0 = rowBase + wm * 32 + (lane >> 2);
    const int colb = wn * 32 + (lane & 3) * 2;
#pragma unroll
    for (int nt = 0; nt < 4; nt++) {
        int cc = colb + nt * 8;
        float bx = bias[cc], by = bias[cc + 1];
        float p0 = 0.f, p1 = 0.f, q0 = 0.f, q1 = 0.f;
#pragma unroll
        for (int t = 0; t < 2; t++) {
#pragma unroll
            for (int h = 0; h < 2; h++) {
                int row = r0 + t * 16 + h * 8;
                float y0 = acc[t][nt][h * 2] + bx;
                float y1 = acc[t][nt][h * 2 + 1] + by;
                if (row < n) {
                    *(uint32_t*)(out + (size_t)row * HID + cc) =
                        pack_h2(__float2half_rn(y0), __float2half_rn(y1));
                    p0 += y0; q0 += y0 * y0;
                    p1 += y1; q1 += y1 * y1;
                }
            }
        }
#pragma unroll
        for (int m = 4; m <= 16; m <<= 1) {
            p0 += __shfl_xor_sync(~0u, p0, m);
            p1 += __shfl_xor_sync(~0u, p1, m);
            q0 += __shfl_xor_sync(~0u, q0, m);
            q1 += __shfl_xor_sync(~0u, q1, m);
        }
        if ((lane >> 2) == 0) {
            atomicAdd(&ssum[cc], p0);
            atomicAdd(&ssum[cc + 1], p1);
            atomicAdd(&ssq[cc], q0);
            atomicAdd(&ssq[cc + 1], q1);
        }
    }
    __syncthreads();
    if (tid < 128) {
        atomicAdd(&g_colsum[tid], ssum[tid]);
        atomicAdd(&g_colsq[tid], ssq[tid]);
    }
}

// ---------------- encoder layer 1: fp32 x (K=256) -> fp16 y1, BN stats ----------
// smem: a(16K) w(32K) araw(32K) stats(1K) = 81KB -> 2 CTAs/SM
#define OFF_W 16384
#define OFF_ARAW 49152
#define OFF_ST1 81920
#define ENC1_SMEM (81920 + 1024)
__global__ void __launch_bounds__(256, 2)
k_enc1(const float* __restrict__ A, const float* __restrict__ bias, __half* __restrict__ out,
       int n) {
    extern __shared__ char smem[];
    char* aA = smem;
    float* ssum = (float*)(smem + OFF_ST1);
    float* ssq = ssum + 128;
    const uint32_t sb = smem_u32(smem);
    const int tid = threadIdx.x, lane = tid & 31, wid = tid >> 5;
    const int wm = wid & 1, wn = wid >> 1;
    const int rowBase = blockIdx.x * 64;
    const int Kw = 256;
    const __half* W = g_Bt16;

    if (tid < 128) { ssum[tid] = 0.f; ssq[tid] = 0.f; }

    float acc[2][4][4];
#pragma unroll
    for (int t = 0; t < 2; t++)
#pragma unroll
        for (int nt = 0; nt < 4; nt++)
#pragma unroll
            for (int j = 0; j < 4; j++) acc[t][nt][j] = 0.f;

    // group0: W chunk0; group1: raw fp32 A chunk1 into ARAW
    stage_w_async(W, Kw, 0, sb + OFF_W, tid);
    CP_COMMIT();
#pragma unroll
    for (int it = 0; it < 8; it++) {
        int idx = tid + 256 * it;
        int r = idx >> 5;
        int kk = (idx & 31) * 4;
        int row = rowBase + r;
        int srow = (row < n) ? row : 0;  // clamp; zeroed at convert
        cpasync16(sb + OFF_ARAW + (uint32_t)idx * 16u, A + (size_t)srow * Kw + 128 + kk);
    }
    CP_COMMIT();
    stage_act<0>(A, Kw, 0, rowBase, n, aA, 0, tid);
    CP_WAIT1();  // W0 ready (ARAW may still fly)
    __syncthreads();

    gemm_tile_pipe(sb, sb + OFF_W, acc, wm, wn, lane);

    __syncthreads();  // gemm0 reads done -> W buffer reusable
    stage_w_async(W, Kw, 128, sb + OFF_W, tid);
    CP_COMMIT();
    CP_WAIT1();  // ARAW arrived (W1 is the single pending group)
#pragma unroll
    for (int it = 0; it < 8; it++) {
        int idx = tid + 256 * it;
        int r = idx >> 5;
        int kk = (idx & 31) * 4;
        float4 v = *(const float4*)(smem + OFF_ARAW + (size_t)idx * 16);
        if (rowBase + r >= n) v = make_float4(0.f, 0.f, 0.f, 0.f);
        store_h(v, r, kk, aA);
    }
    CP_WAIT0();
    __syncthreads();
    gemm_tile_pipe(sb, sb + OFF_W, acc, wm, wn, lane);

    enc_epilogue(acc, bias, out, n, rowBase, wm, wn, lane, tid, ssum, ssq);
}

// ---------------- encoder layer 2: fp16 y1 -> BN0+relu -> fp16 y2, BN stats ------
// smem: a(16K) w(32K) stats(1K) = 49KB; regs<=84 -> 3 CTAs/SM
#define OFF_ST2 49152
#define ENC2_SMEM (49152 + 1024)
__global__ void __launch_bounds__(256, 3)
k_enc2(const __half* __restrict__ A, const float* __restrict__ bias,
       __half* __restrict__ out, int n) {
    extern __shared__ char smem[];
    float* ssum = (float*)(smem + OFF_ST2);
    float* ssq = ssum + 128;
    const uint32_t sb = smem_u32(smem);
    const int tid = threadIdx.x, lane = tid & 31, wid = tid >> 5;
    const int wm = wid & 1, wn = wid >> 1;
    const int rowBase = blockIdx.x * 64;

    if (tid < 128) { ssum[tid] = 0.f; ssq[tid] = 0.f; }

    float acc[2][4][4];
#pragma unroll
    for (int t = 0; t < 2; t++)
#pragma unroll
        for (int nt = 0; nt < 4; nt++)
#pragma unroll
            for (int j = 0; j < 4; j++) acc[t][nt][j] = 0.f;

    stage_w_async(g_Bt16 + 32768, 128, 0, sb + OFF_W, tid);
    CP_COMMIT();
    stage_act16<1>(A, 128, rowBase, n, smem, 0, tid);
    CP_WAIT0();
    __syncthreads();

    gemm_tile_simple(sb, sb + OFF_W, acc, wm, wn, lane);

    enc_epilogue(acc, bias, out, n, rowBase, wm, wn, lane, tid, ssum, ssq);
}

// ---------------- fused 4-GEMM attention kernel ----------------
// smem: a(16K) w(32K) = 48KB; regs<=84 -> 3 CTAs/SM
#define FUS_SMEM 49152
__global__ void __launch_bounds__(256, 3)
k_fused(const __half* __restrict__ A, const float* __restrict__ bv,
        const float* __restrict__ bo, float* __restrict__ out, int n) {
    extern __shared__ char smem[];
    const uint32_t sb = smem_u32(smem);
    const int tid = threadIdx.x, lane = tid & 31, wid = tid >> 5;
    const int wm = wid & 1, wn = wid >> 1;
    const int rowBase = blockIdx.x * 64;

    const int woffs[4] = {49152, 65536, 81920, 98304};
    const float* biases[4] = {bv, bo, bv + HID, bo + HID};

    // prefetch W0 + initial act stage (BN#1 + relu on y2, fp16 in)
    stage_w_async(g_Bt16 + woffs[0], 128, 0, sb + OFF_W, tid);
    CP_COMMIT();
    stage_act16<1>(A, 128, rowBase, n, smem, 1, tid);
    CP_WAIT0();
    __syncthreads();

    float mk[2][2];
#pragma unroll
    for (int t = 0; t < 2; t++)
#pragma unroll
        for (int h = 0; h < 2; h++) {
            int row = rowBase + wm * 32 + t * 16 + h * 8 + (lane >> 2);
            mk[t][h] = (row < n) ? g_mask[row] : 0.f;
        }

    for (int s = 0; s < 4; s++) {
        float acc[2][4][4];
#pragma unroll
        for (int t = 0; t < 2; t++)
#pragma unroll
            for (int nt = 0; nt < 4; nt++)
#pragma unroll
                for (int j = 0; j < 4; j++) acc[t][nt][j] = 0.f;

        gemm_tile_simple(sb, sb + OFF_W, acc, wm, wn, lane);
        __syncthreads();  // all reads of act+W done -> safe to overwrite both

        if (s < 3) {
            stage_w_async(g_Bt16 + woffs[s + 1], 128, 0, sb + OFF_W, tid);
            CP_COMMIT();
        }

        const float* bias = biases[s];
        const bool isMask = (s & 1) == 0;
        const bool last = (s == 3);
        const int colb = wn * 32 + (lane & 3) * 2;
#pragma unroll
        for (int nt = 0; nt < 4; nt++) {
            int cc = colb + nt * 8;
            float bx = bias[cc], by = bias[cc + 1];
#pragma unroll
            for (int t = 0; t < 2; t++) {
#pragma unroll
                for (int h = 0; h < 2; h++) {
                    float y0 = acc[t][nt][h * 2] + bx;
                    float y1 = acc[t][nt][h * 2 + 1] + by;
                    if (isMask) {
                        y0 *= mk[t][h];
                        y1 *= mk[t][h];
                    } else {
                        y0 = fmaxf(y0, 0.f);
                        y1 = fmaxf(y1, 0.f);
                    }
                    int rl = wm * 32 + t * 16 + h * 8 + (lane >> 2);
                    if (last) {
                        int row = rowBase + rl;
                        if (row < n)
                            *(float2*)(out + (size_t)row * HID + cc) = make_float2(y0, y1);
                    } else {
                        uint32_t hi = pack_h2(__float2half_rn(y0), __float2half_rn(y1));
                        *(uint32_t*)(smem + swzb(rl, cc * 2)) = hi;
                    }
                }
            }
        }
        if (!last) {
            CP_WAIT0();
            __syncthreads();  // epilogue visible + next weights ready
        }
    }
}

// ---------------- launch ----------------
extern "C" void kernel_launch(void* const* d_in, const int* in_sizes, int n_in,
                              void* d_out, int out_size) {
    const float* x   = (const float*)d_in[0];
    const int*   ei  = (const int*)d_in[1];
    const float* W1  = (const float*)d_in[2];
    const float* b1  = (const float*)d_in[3];
    const float* g1  = (const float*)d_in[4];
    const float* be1 = (const float*)d_in[5];
    const float* W2  = (const float*)d_in[6];
    const float* b2  = (const float*)d_in[7];
    const float* g2  = (const float*)d_in[8];
    const float* be2 = (const float*)d_in[9];
    // d_in[10..13] = Wq,bq,Wk,bk : mathematically unused (softmax over dst sums to 1)
    const float* Wv  = (const float*)d_in[14];
    const float* bv  = (const float*)d_in[15];
    const float* Wo  = (const float*)d_in[16];
    const float* bo  = (const float*)d_in[17];
    float* out = (float*)d_out;

    const int n = in_sizes[0] / 256;
    const int E = in_sizes[1] / 2;
    const int* dst = ei + E;

    __half *bufA, *bufB;
    float* mask;
    cudaGetSymbolAddress((void**)&bufA, g_hbufA);
    cudaGetSymbolAddress((void**)&bufB, g_hbufB);
    cudaGetSymbolAddress((void**)&mask, g_mask);

    cudaFuncSetAttribute(k_enc1, cudaFuncAttributeMaxDynamicSharedMemorySize, ENC1_SMEM);
    cudaFuncSetAttribute(k_enc2, cudaFuncAttributeMaxDynamicSharedMemorySize, ENC2_SMEM);
    cudaFuncSetAttribute(k_fused, cudaFuncAttributeMaxDynamicSharedMemorySize, FUS_SMEM);

    const int gblk = (n + 63) / 64;

    k_prep<<<dim3(128, 6), 256>>>(W1, W2, Wv, Wo);
    k_init<<<(n + 255) / 256, 256>>>(mask, n);
    k_scatter<<<(E + 255) / 256, 256>>>(dst, E, mask);

    // encoder layer 1: y1 = x @ W1 + b1 (stats fused) -> BN #0
    k_enc1<<<gblk, 256, ENC1_SMEM>>>(x, b1, bufA, n);
    k_finalize<<<1, 128>>>(g1, be1, 0, n);

    // encoder layer 2: y2 = relu(bn0(y1)) @ W2 + b2 (stats fused) -> BN #1
    k_enc2<<<gblk, 256, ENC2_SMEM>>>(bufA, b2, bufB, n);
    k_finalize<<<1, 128>>>(g2, be2, 1, n);

    // fused attention stack (Wv0/mask -> Wo0/relu -> Wv1/mask -> Wo1/relu)
    k_fused<<<gblk, 256, FUS_SMEM>>>(bufB, bv, bo, out, n);
}